// round 1
// baseline (speedup 1.0000x reference)
#include <cuda_runtime.h>
#include <mma.h>
#include <math.h>

using namespace nvcuda;

#define BATCH 64
#define SEQ   1024
#define H1D   1024
#define ATT   1024
#define H2D   1024
#define MTOT  (SEQ * BATCH)   // 65536 rows of the big GEMM

// ---------------- scratch (no allocations allowed) ----------------
__device__ float g_c[BATCH * ATT];      // c[b,a] = W2.hs_b + b1 + b2
__device__ float g_score[BATCH * SEQ];  // pre-softmax scores, [b][s]

// ============================================================================
// Kernel A: c[b,a] = sum_h W2[a,h] * hs_b[b,h] + W1_b[a] + W2_b[a]
// hs is (L=2, B, 512); hs_b[b, l*512+d] = hs[l, b, d]
// grid (64, 128), block 256 (8 warps -> 8 'a' rows per block)
// ============================================================================
__global__ void precompute_c_kernel(const float* __restrict__ hs,
                                    const float* __restrict__ W2_w,
                                    const float* __restrict__ W1_b,
                                    const float* __restrict__ W2_b) {
    __shared__ float hsb[H2D];
    int b = blockIdx.x;
    for (int h = threadIdx.x; h < H2D; h += blockDim.x) {
        hsb[h] = hs[(h >> 9) * (BATCH * 512) + b * 512 + (h & 511)];
    }
    __syncthreads();
    int warp = threadIdx.x >> 5, lane = threadIdx.x & 31;
    int a = blockIdx.y * 8 + warp;
    const float* w2 = W2_w + a * H2D;
    float acc = 0.f;
    for (int h = lane; h < H2D; h += 32) acc += w2[h] * hsb[h];
    #pragma unroll
    for (int o = 16; o; o >>= 1) acc += __shfl_xor_sync(0xffffffffu, acc, o);
    if (lane == 0) g_c[b * ATT + a] = acc + W1_b[a] + W2_b[a];
}

// ============================================================================
// Kernel B: fused TF32 GEMM + tanh + V-reduction.
// score[r] = sum_a V[a] * tanh( sum_h ht[r,h]*W1[a,h] + c[r%64, a] )
// Rows r = s*64+b (ht is (S,B,H1) contiguous). Block tile 128 rows x full ATT
// (8 n-tiles of 128 iterated in-block), K staged 32 at a time.
// 8 warps: 4x2 warp grid, each warp 32x64 via 2x4 wmma 16x16x8 tf32 frags.
// smem union: [At 128x36 | Bt 128x36] vs [Ct 128x132]  (67584 B dynamic)
// ============================================================================
#define BM   128
#define KC   32
#define LDAB 36
#define LDC  132
#define SMEM_B_BYTES (BM * LDC * 4)   // 67584, > At+Bt (36864)

__global__ void __launch_bounds__(256, 2)
energy_score_kernel(const float* __restrict__ ht,
                    const float* __restrict__ W1_w,
                    const float* __restrict__ V_w) {
    extern __shared__ float smem[];
    float* At = smem;                 // [BM][LDAB] row-major (m,k)
    float* Bt = smem + BM * LDAB;     // [128][LDAB] as (n,k)  == col-major B
    float* Ct = smem;                 // union, [BM][LDC]
    __shared__ float score_s[BM];

    int tid  = threadIdx.x;
    int warp = tid >> 5, lane = tid & 31;
    int wm = warp >> 1;               // 0..3 : 32-row strip
    int wn = warp & 1;                // 0..1 : 64-col strip
    int r0 = blockIdx.x * BM;

    if (tid < BM) score_s[tid] = 0.f;

    wmma::fragment<wmma::accumulator, 16, 16, 8, float> acc[2][4];

    for (int nt = 0; nt < 8; nt++) {
        int n0 = nt * 128;
        #pragma unroll
        for (int i = 0; i < 2; i++)
            #pragma unroll
            for (int j = 0; j < 4; j++) wmma::fill_fragment(acc[i][j], 0.f);

        for (int k0 = 0; k0 < H1D; k0 += KC) {
            // stage A (ht rows) and B (W1 rows, kept (n,k) = col-major for wmma)
            int mrow = tid >> 3;            // 0..31
            int kq   = (tid & 7) * 4;       // 0,4,...,28
            #pragma unroll
            for (int rr = 0; rr < 4; rr++) {
                int m = mrow + rr * 32;
                float4 av = *reinterpret_cast<const float4*>(
                    &ht[(r0 + m) * H1D + k0 + kq]);
                float* da = &At[m * LDAB + kq];
                da[0] = wmma::__float_to_tf32(av.x);
                da[1] = wmma::__float_to_tf32(av.y);
                da[2] = wmma::__float_to_tf32(av.z);
                da[3] = wmma::__float_to_tf32(av.w);
                float4 bv = *reinterpret_cast<const float4*>(
                    &W1_w[(n0 + m) * H1D + k0 + kq]);
                float* db = &Bt[m * LDAB + kq];
                db[0] = wmma::__float_to_tf32(bv.x);
                db[1] = wmma::__float_to_tf32(bv.y);
                db[2] = wmma::__float_to_tf32(bv.z);
                db[3] = wmma::__float_to_tf32(bv.w);
            }
            __syncthreads();
            #pragma unroll
            for (int ks = 0; ks < 4; ks++) {
                wmma::fragment<wmma::matrix_a, 16, 16, 8,
                               wmma::precision::tf32, wmma::row_major> af[2];
                wmma::fragment<wmma::matrix_b, 16, 16, 8,
                               wmma::precision::tf32, wmma::col_major> bf[4];
                #pragma unroll
                for (int i = 0; i < 2; i++)
                    wmma::load_matrix_sync(af[i],
                        &At[(wm * 32 + i * 16) * LDAB + ks * 8], LDAB);
                #pragma unroll
                for (int j = 0; j < 4; j++)
                    wmma::load_matrix_sync(bf[j],
                        &Bt[(wn * 64 + j * 16) * LDAB + ks * 8], LDAB);
                #pragma unroll
                for (int i = 0; i < 2; i++)
                    #pragma unroll
                    for (int j = 0; j < 4; j++)
                        wmma::mma_sync(acc[i][j], af[i], bf[j], acc[i][j]);
            }
            __syncthreads();   // done with this stage before refill/union use
        }

        // drain accumulators to smem tile
        #pragma unroll
        for (int i = 0; i < 2; i++)
            #pragma unroll
            for (int j = 0; j < 4; j++)
                wmma::store_matrix_sync(
                    &Ct[(wm * 32 + i * 16) * LDC + wn * 64 + j * 16],
                    acc[i][j], LDC, wmma::mem_row_major);
        __syncthreads();

        // epilogue: warp w owns rows 16w..16w+15; each lane covers 4 columns
        float vv0 = V_w[n0 + lane];
        float vv1 = V_w[n0 + lane + 32];
        float vv2 = V_w[n0 + lane + 64];
        float vv3 = V_w[n0 + lane + 96];
        #pragma unroll 4
        for (int rr = 0; rr < 16; rr++) {
            int i = warp * 16 + rr;
            int b = (r0 + i) & 63;
            const float* crow = &g_c[b * ATT + n0];
            float p = vv0 * tanhf(Ct[i * LDC + lane]      + crow[lane])
                    + vv1 * tanhf(Ct[i * LDC + lane + 32] + crow[lane + 32])
                    + vv2 * tanhf(Ct[i * LDC + lane + 64] + crow[lane + 64])
                    + vv3 * tanhf(Ct[i * LDC + lane + 96] + crow[lane + 96]);
            #pragma unroll
            for (int o = 16; o; o >>= 1) p += __shfl_xor_sync(0xffffffffu, p, o);
            if (lane == 0) score_s[i] += p;
        }
        __syncthreads();   // Ct free for next n-tile staging / final read
    }

    if (tid < BM) {
        int r = r0 + tid;                    // r = s*64 + b
        g_score[(r & 63) * SEQ + (r >> 6)] = score_s[tid];
    }
}

// ============================================================================
// Kernel C: softmax over S per batch. grid 64, block 256 (4 elems/thread)
// ============================================================================
__global__ void softmax_kernel(float* __restrict__ attn_out) {
    __shared__ float red[8];
    int b = blockIdx.x, tid = threadIdx.x;
    int lane = tid & 31, warp = tid >> 5;
    float4 v = *reinterpret_cast<const float4*>(&g_score[b * SEQ + tid * 4]);
    float mx = fmaxf(fmaxf(v.x, v.y), fmaxf(v.z, v.w));
    #pragma unroll
    for (int o = 16; o; o >>= 1) mx = fmaxf(mx, __shfl_xor_sync(0xffffffffu, mx, o));
    if (lane == 0) red[warp] = mx;
    __syncthreads();
    mx = red[0];
    #pragma unroll
    for (int i = 1; i < 8; i++) mx = fmaxf(mx, red[i]);
    float e0 = expf(v.x - mx), e1 = expf(v.y - mx);
    float e2 = expf(v.z - mx), e3 = expf(v.w - mx);
    float s = e0 + e1 + e2 + e3;
    #pragma unroll
    for (int o = 16; o; o >>= 1) s += __shfl_xor_sync(0xffffffffu, s, o);
    __syncthreads();
    if (lane == 0) red[warp] = s;
    __syncthreads();
    s = 0.f;
    #pragma unroll
    for (int i = 0; i < 8; i++) s += red[i];
    float inv = 1.f / s;
    float4 o4 = make_float4(e0 * inv, e1 * inv, e2 * inv, e3 * inv);
    *reinterpret_cast<float4*>(&attn_out[b * SEQ + tid * 4]) = o4;
}

// ============================================================================
// Kernel D: context[b,h] = sum_s w[b,s] * ht[s,b,h]. grid (8,64), block 128
// ============================================================================
__global__ void context_kernel(const float* __restrict__ ht,
                               const float* __restrict__ attn,
                               float* __restrict__ out_ctx) {
    __shared__ float w[SEQ];
    int b = blockIdx.y;
    int h = blockIdx.x * 128 + threadIdx.x;
    for (int s = threadIdx.x; s < SEQ; s += 128) w[s] = attn[b * SEQ + s];
    __syncthreads();
    const float* p = ht + b * H1D + h;
    float acc = 0.f;
    #pragma unroll 8
    for (int s = 0; s < SEQ; s++) acc += w[s] * p[s * (BATCH * H1D)];
    out_ctx[b * H1D + h] = acc;
}

// ============================================================================
extern "C" void kernel_launch(void* const* d_in, const int* in_sizes, int n_in,
                              void* d_out, int out_size) {
    const float* hs   = (const float*)d_in[0];
    const float* ht   = (const float*)d_in[1];
    const float* W1_w = (const float*)d_in[2];
    const float* W1_b = (const float*)d_in[3];
    const float* W2_w = (const float*)d_in[4];
    const float* W2_b = (const float*)d_in[5];
    const float* V_w  = (const float*)d_in[6];
    // d_in[7] = V_b: constant shift, cancels in softmax.

    float* out_ctx  = (float*)d_out;            // context_vector (B, H1) = 65536
    float* out_attn = (float*)d_out + BATCH * H1D;  // attention_weights (B, S, 1)

    precompute_c_kernel<<<dim3(BATCH, ATT / 8), 256>>>(hs, W2_w, W1_b, W2_b);

    cudaFuncSetAttribute(energy_score_kernel,
                         cudaFuncAttributeMaxDynamicSharedMemorySize,
                         SMEM_B_BYTES);
    energy_score_kernel<<<MTOT / BM, 256, SMEM_B_BYTES>>>(ht, W1_w, V_w);

    softmax_kernel<<<BATCH, 256>>>(out_attn);

    context_kernel<<<dim3(H1D / 128, BATCH), 128>>>(ht, out_attn, out_ctx);
}

// round 3
// speedup vs baseline: 2.2139x; 2.2139x over previous
#include <cuda_runtime.h>
#include <cstdint>
#include <cstddef>

#define BATCH 64
#define SEQ   1024
#define H1D   1024
#define ATT   1024
#define H2D   1024
#define MTOT  (SEQ * BATCH)

// ---------------- device scratch (no allocations allowed) ----------------
__device__ float g_cT[ATT * BATCH];      // c transposed: g_cT[a*64 + b]
__device__ float g_score[BATCH * SEQ];   // pre-softmax scores [b][s]
__device__ float g_part[4][BATCH * H1D]; // context partials over s-quarters

__device__ __forceinline__ float tanh_fast(float x) {
    float y;
    asm("tanh.approx.f32 %0, %1;" : "=f"(y) : "f"(x));
    return y;
}
__device__ __forceinline__ void cp16(uint32_t dst, const void* src) {
    asm volatile("cp.async.cg.shared.global [%0], [%1], 16;" :: "r"(dst), "l"(src));
}
__device__ __forceinline__ uint32_t smem_u32(const void* p) {
    uint32_t a;
    asm("{ .reg .u64 t; cvta.to.shared.u64 t, %1; cvt.u32.u64 %0, t; }"
        : "=r"(a) : "l"(p));
    return a;
}

// ============================================================================
// Kernel A: c[b,a] -> transposed g_cT[a*64+b]
// ============================================================================
__global__ void precompute_c_kernel(const float* __restrict__ hs,
                                    const float* __restrict__ W2_w,
                                    const float* __restrict__ W1_b,
                                    const float* __restrict__ W2_b) {
    __shared__ float hsb[H2D];
    int b = blockIdx.x;
    for (int h = threadIdx.x; h < H2D; h += blockDim.x)
        hsb[h] = hs[(h >> 9) * (BATCH * 512) + b * 512 + (h & 511)];
    __syncthreads();
    int warp = threadIdx.x >> 5, lane = threadIdx.x & 31;
    int a = blockIdx.y * 8 + warp;
    const float* w2 = W2_w + (size_t)a * H2D;
    float acc = 0.f;
    for (int h = lane; h < H2D; h += 32) acc += w2[h] * hsb[h];
    #pragma unroll
    for (int o = 16; o; o >>= 1) acc += __shfl_xor_sync(0xffffffffu, acc, o);
    if (lane == 0) g_cT[a * BATCH + b] = acc + W1_b[a] + W2_b[a];
}

// ============================================================================
// Kernel B: fused energy/score GEMM via pipelined mma.sync (tf32).
//   CTA tile: 128 rows x 256 cols per n-tile, NT=4 n-tiles, KC=32.
//   8 warps, warp tile 64x64 (m16n8k8). 3-stage cp.async pipeline.
//   Epilogue (per n-tile, in registers): sc += V[col]*tanh(d + c[brow,col]).
// ============================================================================
#define KC      32
#define LDK     36                         // floats per staged row (pad 4)
#define A_F     (128 * LDK)                // 4608 floats
#define B_F     (256 * LDK)                // 9216 floats
#define STAGE_F (A_F + B_F)                // 13824 floats = 55296 B
#define NSTAGE  3
#define DYN_BYTES (NSTAGE * STAGE_F * 4)   // 165888 B

__device__ __forceinline__ void mma_tf32(float d[4], uint32_t a0, uint32_t a1,
                                         uint32_t a2, uint32_t a3,
                                         uint32_t b0, uint32_t b1) {
    asm volatile(
        "mma.sync.aligned.m16n8k8.row.col.f32.tf32.tf32.f32 "
        "{%0,%1,%2,%3}, {%4,%5,%6,%7}, {%8,%9}, {%0,%1,%2,%3};"
        : "+f"(d[0]), "+f"(d[1]), "+f"(d[2]), "+f"(d[3])
        : "r"(a0), "r"(a1), "r"(a2), "r"(a3), "r"(b0), "r"(b1));
}

__global__ void __launch_bounds__(256, 1)
energy_mma_kernel(const float* __restrict__ ht, const float* __restrict__ W1,
                  const float* __restrict__ V_w) {
    extern __shared__ float dyn[];
    __shared__ float sV[ATT];
    __shared__ float part[4][128];

    const int tid  = threadIdx.x;
    const int warp = tid >> 5, lane = tid & 31;
    const int wm = warp >> 2;          // 0..1 : 64-row strip
    const int wn = warp & 3;           // 0..3 : 64-col strip
    const int q  = lane >> 2;          // 0..7
    const int c  = lane & 3;           // 0..3
    const int r0 = blockIdx.x * 128;

    for (int i = tid; i < ATT; i += 256) sV[i] = V_w[i];

    // per-thread staging map: kq fixed, 4 A-rows + 8 B-rows
    const int kq   = tid & 7;
    const int rbase = tid >> 3;               // 0..31
    const uint32_t sb0 = smem_u32(dyn);

    // accumulators + per-row score partials
    float d[4][8][4];
    #pragma unroll
    for (int mi = 0; mi < 4; mi++)
        #pragma unroll
        for (int ni = 0; ni < 8; ni++)
            #pragma unroll
            for (int r = 0; r < 4; r++) d[mi][ni][r] = 0.f;
    float sc[8];
    #pragma unroll
    for (int i = 0; i < 8; i++) sc[i] = 0.f;

    // ---- stage issuer: fills buffer st with (k0, n0) slab ----
    auto issue = [&](int f) {
        const int st = f % NSTAGE;
        const int k0 = (f & 31) * KC;
        const int n0 = (f >> 5) * 256;
        const uint32_t base = sb0 + (uint32_t)(st * STAGE_F * 4);
        const float* srcA = ht + (size_t)(r0 + rbase) * H1D + k0 + kq * 4;
        #pragma unroll
        for (int i = 0; i < 4; i++) {
            cp16(base + (uint32_t)((rbase + i * 32) * (LDK * 4) + kq * 16),
                 srcA + (size_t)(i * 32) * H1D);
        }
        const float* srcB = W1 + (size_t)(n0 + rbase) * H1D + k0 + kq * 4;
        const uint32_t bbase = base + A_F * 4;
        #pragma unroll
        for (int j = 0; j < 8; j++) {
            cp16(bbase + (uint32_t)((rbase + j * 32) * (LDK * 4) + kq * 16),
                 srcB + (size_t)(j * 32) * H1D);
        }
    };

    issue(0); asm volatile("cp.async.commit_group;" ::: "memory");
    issue(1); asm volatile("cp.async.commit_group;" ::: "memory");

    const int F = 4 * 32;   // nt * k-chunks
    for (int f = 0; f < F; f++) {
        asm volatile("cp.async.wait_group 1;" ::: "memory");
        __syncthreads();

        if (f + 2 < F) issue(f + 2);
        asm volatile("cp.async.commit_group;" ::: "memory");

        // ---- compute on stage f ----
        const int st = f % NSTAGE;
        const uint32_t* As =
            reinterpret_cast<const uint32_t*>(dyn + st * STAGE_F);
        const uint32_t* Bs = As + A_F;

        #pragma unroll
        for (int kk = 0; kk < 4; kk++) {
            const int kb = kk * 8;
            uint32_t af[4][4];
            #pragma unroll
            for (int mi = 0; mi < 4; mi++) {
                const uint32_t* p =
                    &As[(wm * 64 + mi * 16 + q) * LDK + kb + c];
                af[mi][0] = p[0];
                af[mi][1] = p[8 * LDK];
                af[mi][2] = p[4];
                af[mi][3] = p[8 * LDK + 4];
            }
            uint32_t bf[8][2];
            #pragma unroll
            for (int ni = 0; ni < 8; ni++) {
                const uint32_t* p =
                    &Bs[(wn * 64 + ni * 8 + q) * LDK + kb + c];
                bf[ni][0] = p[0];
                bf[ni][1] = p[4];
            }
            #pragma unroll
            for (int mi = 0; mi < 4; mi++)
                #pragma unroll
                for (int ni = 0; ni < 8; ni++)
                    mma_tf32(d[mi][ni], af[mi][0], af[mi][1], af[mi][2],
                             af[mi][3], bf[ni][0], bf[ni][1]);
        }

        // ---- end of n-tile: fused tanh + V-dot, reset accumulators ----
        if ((f & 31) == 31) {
            const int n0 = (f >> 5) * 256;
            #pragma unroll
            for (int mi = 0; mi < 4; mi++) {
                const int rA = wm * 64 + mi * 16 + q;       // local row
                const int bA = rA & 63;
                const int bB = (rA + 8) & 63;
                float accA = 0.f, accB = 0.f;
                #pragma unroll
                for (int ni = 0; ni < 8; ni++) {
                    const int col = n0 + wn * 64 + ni * 8 + 2 * c;
                    const float v0 = sV[col], v1 = sV[col + 1];
                    const float* cb0 = &g_cT[col * BATCH];
                    const float* cb1 = &g_cT[(col + 1) * BATCH];
                    accA += v0 * tanh_fast(d[mi][ni][0] + __ldg(cb0 + bA))
                          + v1 * tanh_fast(d[mi][ni][1] + __ldg(cb1 + bA));
                    accB += v0 * tanh_fast(d[mi][ni][2] + __ldg(cb0 + bB))
                          + v1 * tanh_fast(d[mi][ni][3] + __ldg(cb1 + bB));
                    d[mi][ni][0] = 0.f; d[mi][ni][1] = 0.f;
                    d[mi][ni][2] = 0.f; d[mi][ni][3] = 0.f;
                }
                sc[mi * 2]     += accA;
                sc[mi * 2 + 1] += accB;
            }
        }
    }

    // ---- final reduction: quad shfl, then across wn warps via smem ----
    #pragma unroll
    for (int mi = 0; mi < 4; mi++)
        #pragma unroll
        for (int h = 0; h < 2; h++) {
            float v = sc[mi * 2 + h];
            v += __shfl_xor_sync(0xffffffffu, v, 1);
            v += __shfl_xor_sync(0xffffffffu, v, 2);
            if (c == 0)
                part[wn][wm * 64 + mi * 16 + q + 8 * h] = v;
        }
    __syncthreads();
    if (tid < 128) {
        float s = part[0][tid] + part[1][tid] + part[2][tid] + part[3][tid];
        int gr = r0 + tid;
        g_score[(gr & 63) * SEQ + (gr >> 6)] = s;
    }
}

// ============================================================================
// Kernel C: softmax over S per batch
// ============================================================================
__global__ void softmax_kernel(float* __restrict__ attn_out) {
    __shared__ float red[8];
    int b = blockIdx.x, tid = threadIdx.x;
    int lane = tid & 31, warp = tid >> 5;
    float4 v = *reinterpret_cast<const float4*>(&g_score[b * SEQ + tid * 4]);
    float mx = fmaxf(fmaxf(v.x, v.y), fmaxf(v.z, v.w));
    #pragma unroll
    for (int o = 16; o; o >>= 1) mx = fmaxf(mx, __shfl_xor_sync(0xffffffffu, mx, o));
    if (lane == 0) red[warp] = mx;
    __syncthreads();
    mx = red[0];
    #pragma unroll
    for (int i = 1; i < 8; i++) mx = fmaxf(mx, red[i]);
    float e0 = expf(v.x - mx), e1 = expf(v.y - mx);
    float e2 = expf(v.z - mx), e3 = expf(v.w - mx);
    float s = e0 + e1 + e2 + e3;
    #pragma unroll
    for (int o = 16; o; o >>= 1) s += __shfl_xor_sync(0xffffffffu, s, o);
    __syncthreads();
    if (lane == 0) red[warp] = s;
    __syncthreads();
    s = 0.f;
    #pragma unroll
    for (int i = 0; i < 8; i++) s += red[i];
    float inv = 1.f / s;
    float4 o4 = make_float4(e0 * inv, e1 * inv, e2 * inv, e3 * inv);
    *reinterpret_cast<float4*>(&attn_out[b * SEQ + tid * 4]) = o4;
}

// ============================================================================
// Kernel D: context partials over s-quarters, then combine
// ============================================================================
__global__ void context_part_kernel(const float* __restrict__ ht,
                                    const float* __restrict__ attn) {
    __shared__ float w[256];
    int b = blockIdx.y;
    int h = blockIdx.x * 128 + threadIdx.x;
    int s0 = blockIdx.z * 256;
    for (int s = threadIdx.x; s < 256; s += 128) w[s] = attn[b * SEQ + s0 + s];
    __syncthreads();
    const float* p = ht + (size_t)s0 * (BATCH * H1D) + b * H1D + h;
    float a0 = 0.f, a1 = 0.f, a2 = 0.f, a3 = 0.f;
    #pragma unroll 4
    for (int s = 0; s < 256; s += 4) {
        a0 += w[s]     * p[(size_t)s * (BATCH * H1D)];
        a1 += w[s + 1] * p[(size_t)(s + 1) * (BATCH * H1D)];
        a2 += w[s + 2] * p[(size_t)(s + 2) * (BATCH * H1D)];
        a3 += w[s + 3] * p[(size_t)(s + 3) * (BATCH * H1D)];
    }
    g_part[blockIdx.z][b * H1D + h] = (a0 + a1) + (a2 + a3);
}

__global__ void context_combine_kernel(float* __restrict__ out_ctx) {
    int i = blockIdx.x * 256 + threadIdx.x;
    out_ctx[i] = (g_part[0][i] + g_part[1][i]) + (g_part[2][i] + g_part[3][i]);
}

// ============================================================================
extern "C" void kernel_launch(void* const* d_in, const int* in_sizes, int n_in,
                              void* d_out, int out_size) {
    const float* hs   = (const float*)d_in[0];
    const float* ht   = (const float*)d_in[1];
    const float* W1_w = (const float*)d_in[2];
    const float* W1_b = (const float*)d_in[3];
    const float* W2_w = (const float*)d_in[4];
    const float* W2_b = (const float*)d_in[5];
    const float* V_w  = (const float*)d_in[6];
    // d_in[7] = V_b: constant shift, cancels in softmax.

    float* out_ctx  = (float*)d_out;                 // (B, H1)
    float* out_attn = (float*)d_out + BATCH * H1D;   // (B, S, 1)

    precompute_c_kernel<<<dim3(BATCH, ATT / 8), 256>>>(hs, W2_w, W1_b, W2_b);

    cudaFuncSetAttribute(energy_mma_kernel,
                         cudaFuncAttributeMaxDynamicSharedMemorySize, DYN_BYTES);
    energy_mma_kernel<<<MTOT / 128, 256, DYN_BYTES>>>(ht, W1_w, V_w);

    softmax_kernel<<<BATCH, 256>>>(out_attn);

    context_part_kernel<<<dim3(H1D / 128, BATCH, 4), 128>>>(ht, out_attn);
    context_combine_kernel<<<BATCH * H1D / 256, 256>>>(out_ctx);
}

// round 5
// speedup vs baseline: 2.2775x; 1.0287x over previous
#include <cuda_runtime.h>
#include <cstdint>
#include <cstddef>

#define BATCH 64
#define SEQ   1024
#define H1D   1024
#define ATT   1024
#define H2D   1024
#define MTOT  (SEQ * BATCH)

// ---------------- device scratch (no allocations allowed) ----------------
__device__ float g_cT[ATT * BATCH];      // c transposed: g_cT[a*64 + b]
__device__ float g_score[BATCH * SEQ];   // pre-softmax scores [b][s]
__device__ float g_part[8][BATCH * H1D]; // context partials over s-eighths

__device__ __forceinline__ float tanh_fast(float x) {
    float y;
    asm("tanh.approx.f32 %0, %1;" : "=f"(y) : "f"(x));
    return y;
}
__device__ __forceinline__ void cp16(uint32_t dst, const void* src) {
    asm volatile("cp.async.cg.shared.global [%0], [%1], 16;" :: "r"(dst), "l"(src));
}
__device__ __forceinline__ uint32_t smem_u32(const void* p) {
    uint32_t a;
    asm("{ .reg .u64 t; cvta.to.shared.u64 t, %1; cvt.u32.u64 %0, t; }"
        : "=r"(a) : "l"(p));
    return a;
}
__device__ __forceinline__ void ldsm_x4(uint32_t r[4], uint32_t addr) {
    asm volatile("ldmatrix.sync.aligned.m8n8.x4.shared.b16 {%0,%1,%2,%3}, [%4];"
                 : "=r"(r[0]), "=r"(r[1]), "=r"(r[2]), "=r"(r[3]) : "r"(addr));
}

// ============================================================================
// Kernel A: c[b,a] -> transposed g_cT[a*64+b]
// ============================================================================
__global__ void precompute_c_kernel(const float* __restrict__ hs,
                                    const float* __restrict__ W2_w,
                                    const float* __restrict__ W1_b,
                                    const float* __restrict__ W2_b) {
    __shared__ float hsb[H2D];
    int b = blockIdx.x;
    for (int h = threadIdx.x; h < H2D; h += blockDim.x)
        hsb[h] = hs[(h >> 9) * (BATCH * 512) + b * 512 + (h & 511)];
    __syncthreads();
    int warp = threadIdx.x >> 5, lane = threadIdx.x & 31;
    int a = blockIdx.y * 8 + warp;
    const float* w2 = W2_w + (size_t)a * H2D;
    float acc = 0.f;
    for (int h = lane; h < H2D; h += 32) acc += w2[h] * hsb[h];
    #pragma unroll
    for (int o = 16; o; o >>= 1) acc += __shfl_xor_sync(0xffffffffu, acc, o);
    if (lane == 0) g_cT[a * BATCH + b] = acc + W1_b[a] + W2_b[a];
}

// ============================================================================
// Kernel B: fused energy/score GEMM via pipelined mma.sync (tf32) + ldmatrix.
//   CTA tile: 128 rows x 256 cols per n-tile, NT=4, KC=32, 3-stage cp.async.
//   8 warps, warp tile 64x64 (m16n8k8). Fragments via ldmatrix.x4 (b16 view).
// ============================================================================
#define KC      32
#define LDK     36                         // floats per staged row (pad 4)
#define A_F     (128 * LDK)                // 4608 floats
#define B_F     (256 * LDK)                // 9216 floats
#define STAGE_F (A_F + B_F)                // 13824 floats = 55296 B
#define NSTAGE  3
#define DYN_BYTES (NSTAGE * STAGE_F * 4)   // 165888 B

__device__ __forceinline__ void mma_tf32(float d[4], uint32_t a0, uint32_t a1,
                                         uint32_t a2, uint32_t a3,
                                         uint32_t b0, uint32_t b1) {
    asm volatile(
        "mma.sync.aligned.m16n8k8.row.col.f32.tf32.tf32.f32 "
        "{%0,%1,%2,%3}, {%4,%5,%6,%7}, {%8,%9}, {%0,%1,%2,%3};"
        : "+f"(d[0]), "+f"(d[1]), "+f"(d[2]), "+f"(d[3])
        : "r"(a0), "r"(a1), "r"(a2), "r"(a3), "r"(b0), "r"(b1));
}

__global__ void __launch_bounds__(256, 1)
energy_mma_kernel(const float* __restrict__ ht, const float* __restrict__ W1,
                  const float* __restrict__ V_w) {
    extern __shared__ float dyn[];
    __shared__ float sV[ATT];
    __shared__ float part[4][128];

    const int tid  = threadIdx.x;
    const int warp = tid >> 5, lane = tid & 31;
    const int wm = warp >> 2;          // 0..1 : 64-row strip
    const int wn = warp & 3;           // 0..3 : 64-col strip
    const int q  = lane >> 2;          // 0..7
    const int c  = lane & 3;           // 0..3
    const int r0 = blockIdx.x * 128;

    for (int i = tid; i < ATT; i += 256) sV[i] = V_w[i];

    // per-thread staging map: kq fixed, 4 A-rows + 8 B-rows
    const int kq    = tid & 7;
    const int rbase = tid >> 3;               // 0..31
    const uint32_t sb0 = smem_u32(dyn);

    // ldmatrix per-lane byte offsets (within a stage)
    const int rr = lane & 7;
    const int gA_row = ((lane >> 3) & 1) * 8;   // matrix g&1 -> +8 rows
    const int gA_khi = ((lane >> 4) & 1) * 16;  // matrix g>>1 -> k-hi 16B
    const int gB_row = ((lane >> 4) & 1) * 8;   // B: g>>1 -> +8 n-rows
    const int gB_khi = ((lane >> 3) & 1) * 16;  // B: g&1 -> k-hi 16B
    uint32_t aoff[4], boff[4];
    #pragma unroll
    for (int mi = 0; mi < 4; mi++)
        aoff[mi] = (uint32_t)((wm * 64 + mi * 16 + rr + gA_row) * (LDK * 4) + gA_khi);
    #pragma unroll
    for (int nj = 0; nj < 4; nj++)
        boff[nj] = (uint32_t)((wn * 64 + nj * 16 + rr + gB_row) * (LDK * 4) + gB_khi
                              + A_F * 4);

    // accumulators + per-row score partials
    float d[4][8][4];
    #pragma unroll
    for (int mi = 0; mi < 4; mi++)
        #pragma unroll
        for (int ni = 0; ni < 8; ni++)
            #pragma unroll
            for (int r = 0; r < 4; r++) d[mi][ni][r] = 0.f;
    float sc[8];
    #pragma unroll
    for (int i = 0; i < 8; i++) sc[i] = 0.f;

    auto issue = [&](int f) {
        const int st = f % NSTAGE;
        const int k0 = (f & 31) * KC;
        const int n0 = (f >> 5) * 256;
        const uint32_t base = sb0 + (uint32_t)(st * STAGE_F * 4);
        const float* srcA = ht + (size_t)(r0 + rbase) * H1D + k0 + kq * 4;
        #pragma unroll
        for (int i = 0; i < 4; i++)
            cp16(base + (uint32_t)((rbase + i * 32) * (LDK * 4) + kq * 16),
                 srcA + (size_t)(i * 32) * H1D);
        const float* srcB = W1 + (size_t)(n0 + rbase) * H1D + k0 + kq * 4;
        const uint32_t bbase = base + A_F * 4;
        #pragma unroll
        for (int j = 0; j < 8; j++)
            cp16(bbase + (uint32_t)((rbase + j * 32) * (LDK * 4) + kq * 16),
                 srcB + (size_t)(j * 32) * H1D);
    };

    issue(0); asm volatile("cp.async.commit_group;" ::: "memory");
    issue(1); asm volatile("cp.async.commit_group;" ::: "memory");

    const int F = 4 * 32;   // nt * k-chunks
    for (int f = 0; f < F; f++) {
        asm volatile("cp.async.wait_group 1;" ::: "memory");
        __syncthreads();

        if (f + 2 < F) issue(f + 2);
        asm volatile("cp.async.commit_group;" ::: "memory");

        const uint32_t sbase = sb0 + (uint32_t)((f % NSTAGE) * STAGE_F * 4);

        #pragma unroll
        for (int kk = 0; kk < 4; kk++) {
            const uint32_t kadd = (uint32_t)(kk * 32);
            uint32_t af[4][4];
            #pragma unroll
            for (int mi = 0; mi < 4; mi++)
                ldsm_x4(af[mi], sbase + aoff[mi] + kadd);
            uint32_t bf[8][2];
            #pragma unroll
            for (int nj = 0; nj < 4; nj++) {
                uint32_t t[4];
                ldsm_x4(t, sbase + boff[nj] + kadd);
                bf[nj * 2][0] = t[0]; bf[nj * 2][1] = t[1];
                bf[nj * 2 + 1][0] = t[2]; bf[nj * 2 + 1][1] = t[3];
            }
            #pragma unroll
            for (int mi = 0; mi < 4; mi++)
                #pragma unroll
                for (int ni = 0; ni < 8; ni++)
                    mma_tf32(d[mi][ni], af[mi][0], af[mi][1], af[mi][2],
                             af[mi][3], bf[ni][0], bf[ni][1]);
        }

        // ---- end of n-tile: fused tanh + V-dot, reset accumulators ----
        if ((f & 31) == 31) {
            const int n0 = (f >> 5) * 256;
            #pragma unroll
            for (int mi = 0; mi < 4; mi++) {
                const int rA = wm * 64 + mi * 16 + q;
                const int bA = rA & 63;
                const int bB = (rA + 8) & 63;
                float accA = 0.f, accB = 0.f;
                #pragma unroll
                for (int ni = 0; ni < 8; ni++) {
                    const int col = n0 + wn * 64 + ni * 8 + 2 * c;
                    const float v0 = sV[col], v1 = sV[col + 1];
                    const float* cb0 = &g_cT[col * BATCH];
                    const float* cb1 = &g_cT[(col + 1) * BATCH];
                    accA += v0 * tanh_fast(d[mi][ni][0] + __ldg(cb0 + bA))
                          + v1 * tanh_fast(d[mi][ni][1] + __ldg(cb1 + bA));
                    accB += v0 * tanh_fast(d[mi][ni][2] + __ldg(cb0 + bB))
                          + v1 * tanh_fast(d[mi][ni][3] + __ldg(cb1 + bB));
                    d[mi][ni][0] = 0.f; d[mi][ni][1] = 0.f;
                    d[mi][ni][2] = 0.f; d[mi][ni][3] = 0.f;
                }
                sc[mi * 2]     += accA;
                sc[mi * 2 + 1] += accB;
            }
        }
    }

    // ---- final reduction: quad shfl, then across wn warps via smem ----
    #pragma unroll
    for (int mi = 0; mi < 4; mi++)
        #pragma unroll
        for (int h = 0; h < 2; h++) {
            float v = sc[mi * 2 + h];
            v += __shfl_xor_sync(0xffffffffu, v, 1);
            v += __shfl_xor_sync(0xffffffffu, v, 2);
            if (c == 0)
                part[wn][wm * 64 + mi * 16 + q + 8 * h] = v;
        }
    __syncthreads();
    if (tid < 128) {
        float s = part[0][tid] + part[1][tid] + part[2][tid] + part[3][tid];
        int gr = r0 + tid;
        g_score[(gr & 63) * SEQ + (gr >> 6)] = s;
    }
}

// ============================================================================
// Kernel C: softmax over S per batch
// ============================================================================
__global__ void softmax_kernel(float* __restrict__ attn_out) {
    __shared__ float red[8];
    int b = blockIdx.x, tid = threadIdx.x;
    int lane = tid & 31, warp = tid >> 5;
    float4 v = *reinterpret_cast<const float4*>(&g_score[b * SEQ + tid * 4]);
    float mx = fmaxf(fmaxf(v.x, v.y), fmaxf(v.z, v.w));
    #pragma unroll
    for (int o = 16; o; o >>= 1) mx = fmaxf(mx, __shfl_xor_sync(0xffffffffu, mx, o));
    if (lane == 0) red[warp] = mx;
    __syncthreads();
    mx = red[0];
    #pragma unroll
    for (int i = 1; i < 8; i++) mx = fmaxf(mx, red[i]);
    float e0 = expf(v.x - mx), e1 = expf(v.y - mx);
    float e2 = expf(v.z - mx), e3 = expf(v.w - mx);
    float s = e0 + e1 + e2 + e3;
    #pragma unroll
    for (int o = 16; o; o >>= 1) s += __shfl_xor_sync(0xffffffffu, s, o);
    __syncthreads();
    if (lane == 0) red[warp] = s;
    __syncthreads();
    s = 0.f;
    #pragma unroll
    for (int i = 0; i < 8; i++) s += red[i];
    float inv = 1.f / s;
    float4 o4 = make_float4(e0 * inv, e1 * inv, e2 * inv, e3 * inv);
    *reinterpret_cast<float4*>(&attn_out[b * SEQ + tid * 4]) = o4;
}

// ============================================================================
// Kernel D: context partials over s-eighths, then combine
// ============================================================================
__global__ void context_part_kernel(const float* __restrict__ ht,
                                    const float* __restrict__ attn) {
    __shared__ float w[128];
    int b = blockIdx.y;
    int h = blockIdx.x * 128 + threadIdx.x;
    int s0 = blockIdx.z * 128;
    if (threadIdx.x < 128) w[threadIdx.x] = attn[b * SEQ + s0 + threadIdx.x];
    __syncthreads();
    const float* p = ht + (size_t)s0 * (BATCH * H1D) + b * H1D + h;
    float a0 = 0.f, a1 = 0.f, a2 = 0.f, a3 = 0.f;
    #pragma unroll 4
    for (int s = 0; s < 128; s += 4) {
        a0 += w[s]     * p[(size_t)s * (BATCH * H1D)];
        a1 += w[s + 1] * p[(size_t)(s + 1) * (BATCH * H1D)];
        a2 += w[s + 2] * p[(size_t)(s + 2) * (BATCH * H1D)];
        a3 += w[s + 3] * p[(size_t)(s + 3) * (BATCH * H1D)];
    }
    g_part[blockIdx.z][b * H1D + h] = (a0 + a1) + (a2 + a3);
}

__global__ void context_combine_kernel(float* __restrict__ out_ctx) {
    int i = blockIdx.x * 256 + threadIdx.x;
    float s = 0.f;
    #pragma unroll
    for (int z = 0; z < 8; z++) s += g_part[z][i];
    out_ctx[i] = s;
}

// ============================================================================
extern "C" void kernel_launch(void* const* d_in, const int* in_sizes, int n_in,
                              void* d_out, int out_size) {
    const float* hs   = (const float*)d_in[0];
    const float* ht   = (const float*)d_in[1];
    const float* W1_w = (const float*)d_in[2];
    const float* W1_b = (const float*)d_in[3];
    const float* W2_w = (const float*)d_in[4];
    const float* W2_b = (const float*)d_in[5];
    const float* V_w  = (const float*)d_in[6];
    // d_in[7] = V_b: constant shift, cancels in softmax.

    float* out_ctx  = (float*)d_out;                 // (B, H1)
    float* out_attn = (float*)d_out + BATCH * H1D;   // (B, S, 1)

    precompute_c_kernel<<<dim3(BATCH, ATT / 8), 256>>>(hs, W2_w, W1_b, W2_b);

    cudaFuncSetAttribute(energy_mma_kernel,
                         cudaFuncAttributeMaxDynamicSharedMemorySize, DYN_BYTES);
    energy_mma_kernel<<<MTOT / 128, 256, DYN_BYTES>>>(ht, W1_w, V_w);

    softmax_kernel<<<BATCH, 256>>>(out_attn);

    context_part_kernel<<<dim3(H1D / 128, BATCH, 8), 128>>>(ht, out_attn);
    context_combine_kernel<<<BATCH * H1D / 256, 256>>>(out_ctx);
}

// round 6
// speedup vs baseline: 3.3010x; 1.4494x over previous
#include <cuda_runtime.h>
#include <cuda_fp16.h>
#include <cstdint>
#include <cstddef>

#define BATCH 64
#define SEQ   1024
#define H1D   1024
#define ATT   1024
#define H2D   1024
#define MTOT  (SEQ * BATCH)

// ---------------- device scratch (no allocations allowed) ----------------
__device__ float  g_cT[ATT * BATCH];      // c transposed: g_cT[a*64 + b]
__device__ float  g_score[BATCH * SEQ];   // pre-softmax scores [b][s]
__device__ float  g_part[8][BATCH * H1D]; // context partials over s-eighths
__device__ __half g_htH[(size_t)MTOT * H1D]; // fp16 copy of ht (128 MB)
__device__ __half g_W1H[(size_t)ATT * H1D];  // fp16 copy of W1 (2 MB)

__device__ __forceinline__ float tanh_fast(float x) {
    float y;
    asm("tanh.approx.f32 %0, %1;" : "=f"(y) : "f"(x));
    return y;
}
__device__ __forceinline__ void cp16(uint32_t dst, const void* src) {
    asm volatile("cp.async.cg.shared.global [%0], [%1], 16;" :: "r"(dst), "l"(src));
}
__device__ __forceinline__ uint32_t smem_u32(const void* p) {
    uint32_t a;
    asm("{ .reg .u64 t; cvta.to.shared.u64 t, %1; cvt.u32.u64 %0, t; }"
        : "=r"(a) : "l"(p));
    return a;
}
__device__ __forceinline__ void ldsm_x4(uint32_t r[4], uint32_t addr) {
    asm volatile("ldmatrix.sync.aligned.m8n8.x4.shared.b16 {%0,%1,%2,%3}, [%4];"
                 : "=r"(r[0]), "=r"(r[1]), "=r"(r[2]), "=r"(r[3]) : "r"(addr));
}

// ============================================================================
// Kernel A0: fp32 -> fp16 bulk convert (8 elems/thread)
// ============================================================================
__global__ void f2h_kernel(const float* __restrict__ src, __half* __restrict__ dst) {
    size_t i = ((size_t)blockIdx.x * 256 + threadIdx.x) * 8;
    float4 a = *reinterpret_cast<const float4*>(src + i);
    float4 b = *reinterpret_cast<const float4*>(src + i + 4);
    __half2 h[4];
    h[0] = __floats2half2_rn(a.x, a.y);
    h[1] = __floats2half2_rn(a.z, a.w);
    h[2] = __floats2half2_rn(b.x, b.y);
    h[3] = __floats2half2_rn(b.z, b.w);
    *reinterpret_cast<uint4*>(dst + i) = *reinterpret_cast<uint4*>(h);
}

// ============================================================================
// Kernel A: c[b,a] -> transposed g_cT[a*64+b]
// ============================================================================
__global__ void precompute_c_kernel(const float* __restrict__ hs,
                                    const float* __restrict__ W2_w,
                                    const float* __restrict__ W1_b,
                                    const float* __restrict__ W2_b) {
    __shared__ float hsb[H2D];
    int b = blockIdx.x;
    for (int h = threadIdx.x; h < H2D; h += blockDim.x)
        hsb[h] = hs[(h >> 9) * (BATCH * 512) + b * 512 + (h & 511)];
    __syncthreads();
    int warp = threadIdx.x >> 5, lane = threadIdx.x & 31;
    int a = blockIdx.y * 8 + warp;
    const float* w2 = W2_w + (size_t)a * H2D;
    float acc = 0.f;
    for (int h = lane; h < H2D; h += 32) acc += w2[h] * hsb[h];
    #pragma unroll
    for (int o = 16; o; o >>= 1) acc += __shfl_xor_sync(0xffffffffu, acc, o);
    if (lane == 0) g_cT[a * BATCH + b] = acc + W1_b[a] + W2_b[a];
}

// ============================================================================
// Kernel B: fused energy/score GEMM, fp16 m16n8k16 HMMA (fp32 accumulate).
//   CTA tile: 128 rows x 256 cols per n-tile, NT=4, KC=32 halfs, 4-stage
//   cp.async pipeline, ldmatrix.x4 fragments, 8 warps with 64x64 warp tiles.
// ============================================================================
#define KC       32                      // halfs per k-chunk
#define LDH_B    80                      // bytes per staged row (64 + 16 pad)
#define A_BYTES  (128 * LDH_B)           // 10240
#define B_BYTES  (256 * LDH_B)           // 20480
#define STAGE_BYTES (A_BYTES + B_BYTES)  // 30720
#define NSTAGE   4
#define DYN_BYTES (NSTAGE * STAGE_BYTES) // 122880

__device__ __forceinline__ void mma_f16(float d[4], uint32_t a0, uint32_t a1,
                                        uint32_t a2, uint32_t a3,
                                        uint32_t b0, uint32_t b1) {
    asm volatile(
        "mma.sync.aligned.m16n8k16.row.col.f32.f16.f16.f32 "
        "{%0,%1,%2,%3}, {%4,%5,%6,%7}, {%8,%9}, {%0,%1,%2,%3};"
        : "+f"(d[0]), "+f"(d[1]), "+f"(d[2]), "+f"(d[3])
        : "r"(a0), "r"(a1), "r"(a2), "r"(a3), "r"(b0), "r"(b1));
}

__global__ void __launch_bounds__(256, 1)
energy_mma_kernel(const float* __restrict__ V_w) {
    extern __shared__ char dynsm[];
    __shared__ float sV[ATT];
    __shared__ float part[4][128];

    const int tid  = threadIdx.x;
    const int warp = tid >> 5, lane = tid & 31;
    const int wm = warp >> 2;          // 0..1 : 64-row strip
    const int wn = warp & 3;           // 0..3 : 64-col strip
    const int q  = lane >> 2;          // 0..7
    const int c  = lane & 3;           // 0..3
    const int r0 = blockIdx.x * 128;

    for (int i = tid; i < ATT; i += 256) sV[i] = V_w[i];

    // staging map: row = tid>>2 (0..63), kq = tid&3 (16B segs within 64B row)
    const int srow = tid >> 2;
    const int kq   = tid & 3;
    const uint32_t sb0 = smem_u32(dynsm);

    // ldmatrix per-lane byte offsets (within a stage)
    const int rr = lane & 7;
    const int gA_row = ((lane >> 3) & 1) * 8;   // A: matrix g&1 -> +8 rows
    const int gA_khi = ((lane >> 4) & 1) * 16;  // A: matrix g>>1 -> k hi 16B
    const int gB_row = ((lane >> 4) & 1) * 8;   // B: matrix g>>1 -> +8 n-rows
    const int gB_khi = ((lane >> 3) & 1) * 16;  // B: matrix g&1 -> k hi 16B
    uint32_t aoff[4], boff[4];
    #pragma unroll
    for (int mi = 0; mi < 4; mi++)
        aoff[mi] = (uint32_t)((wm * 64 + mi * 16 + rr + gA_row) * LDH_B + gA_khi);
    #pragma unroll
    for (int nj = 0; nj < 4; nj++)
        boff[nj] = (uint32_t)(A_BYTES +
                   (wn * 64 + nj * 16 + rr + gB_row) * LDH_B + gB_khi);

    float d[4][8][4];
    #pragma unroll
    for (int mi = 0; mi < 4; mi++)
        #pragma unroll
        for (int ni = 0; ni < 8; ni++)
            #pragma unroll
            for (int r = 0; r < 4; r++) d[mi][ni][r] = 0.f;
    float sc[8];
    #pragma unroll
    for (int i = 0; i < 8; i++) sc[i] = 0.f;

    auto issue = [&](int f) {
        const int st  = f & (NSTAGE - 1);
        const int k0h = (f & 31) * KC;
        const int n0  = (f >> 5) * 256;
        const uint32_t base = sb0 + (uint32_t)(st * STAGE_BYTES);
        #pragma unroll
        for (int i = 0; i < 2; i++) {
            int r = srow + i * 64;
            cp16(base + (uint32_t)(r * LDH_B + kq * 16),
                 g_htH + (size_t)(r0 + r) * H1D + k0h + kq * 8);
        }
        #pragma unroll
        for (int j = 0; j < 4; j++) {
            int r = srow + j * 64;
            cp16(base + (uint32_t)(A_BYTES + r * LDH_B + kq * 16),
                 g_W1H + (size_t)(n0 + r) * H1D + k0h + kq * 8);
        }
    };

    issue(0); asm volatile("cp.async.commit_group;" ::: "memory");
    issue(1); asm volatile("cp.async.commit_group;" ::: "memory");
    issue(2); asm volatile("cp.async.commit_group;" ::: "memory");

    const int F = 4 * 32;   // n-tiles * k-chunks
    for (int f = 0; f < F; f++) {
        asm volatile("cp.async.wait_group 2;" ::: "memory");
        __syncthreads();

        if (f + 3 < F) issue(f + 3);
        asm volatile("cp.async.commit_group;" ::: "memory");

        const uint32_t sbase = sb0 + (uint32_t)((f & (NSTAGE - 1)) * STAGE_BYTES);

        #pragma unroll
        for (int kk = 0; kk < 2; kk++) {            // 2 k-steps of 16
            const uint32_t kadd = (uint32_t)(kk * 32);
            uint32_t af[4][4];
            #pragma unroll
            for (int mi = 0; mi < 4; mi++)
                ldsm_x4(af[mi], sbase + aoff[mi] + kadd);
            uint32_t bf[8][2];
            #pragma unroll
            for (int nj = 0; nj < 4; nj++) {
                uint32_t t[4];
                ldsm_x4(t, sbase + boff[nj] + kadd);
                bf[nj * 2][0] = t[0];     bf[nj * 2][1] = t[1];
                bf[nj * 2 + 1][0] = t[2]; bf[nj * 2 + 1][1] = t[3];
            }
            #pragma unroll
            for (int mi = 0; mi < 4; mi++)
                #pragma unroll
                for (int ni = 0; ni < 8; ni++)
                    mma_f16(d[mi][ni], af[mi][0], af[mi][1], af[mi][2],
                            af[mi][3], bf[ni][0], bf[ni][1]);
        }

        // ---- end of n-tile: fused tanh + V-dot, reset accumulators ----
        if ((f & 31) == 31) {
            const int n0 = (f >> 5) * 256;
            #pragma unroll
            for (int mi = 0; mi < 4; mi++) {
                const int rA = wm * 64 + mi * 16 + q;
                const int bA = rA & 63;
                const int bB = (rA + 8) & 63;
                float accA = 0.f, accB = 0.f;
                #pragma unroll
                for (int ni = 0; ni < 8; ni++) {
                    const int col = n0 + wn * 64 + ni * 8 + 2 * c;
                    const float v0 = sV[col], v1 = sV[col + 1];
                    const float* cb0 = &g_cT[col * BATCH];
                    const float* cb1 = &g_cT[(col + 1) * BATCH];
                    accA += v0 * tanh_fast(d[mi][ni][0] + __ldg(cb0 + bA))
                          + v1 * tanh_fast(d[mi][ni][1] + __ldg(cb1 + bA));
                    accB += v0 * tanh_fast(d[mi][ni][2] + __ldg(cb0 + bB))
                          + v1 * tanh_fast(d[mi][ni][3] + __ldg(cb1 + bB));
                    d[mi][ni][0] = 0.f; d[mi][ni][1] = 0.f;
                    d[mi][ni][2] = 0.f; d[mi][ni][3] = 0.f;
                }
                sc[mi * 2]     += accA;
                sc[mi * 2 + 1] += accB;
            }
        }
    }

    // ---- final reduction: quad shfl, then across wn warps via smem ----
    #pragma unroll
    for (int mi = 0; mi < 4; mi++)
        #pragma unroll
        for (int h = 0; h < 2; h++) {
            float v = sc[mi * 2 + h];
            v += __shfl_xor_sync(0xffffffffu, v, 1);
            v += __shfl_xor_sync(0xffffffffu, v, 2);
            if (c == 0)
                part[wn][wm * 64 + mi * 16 + q + 8 * h] = v;
        }
    __syncthreads();
    if (tid < 128) {
        float s = part[0][tid] + part[1][tid] + part[2][tid] + part[3][tid];
        int gr = r0 + tid;
        g_score[(gr & 63) * SEQ + (gr >> 6)] = s;
    }
}

// ============================================================================
// Kernel C: softmax over S per batch
// ============================================================================
__global__ void softmax_kernel(float* __restrict__ attn_out) {
    __shared__ float red[8];
    int b = blockIdx.x, tid = threadIdx.x;
    int lane = tid & 31, warp = tid >> 5;
    float4 v = *reinterpret_cast<const float4*>(&g_score[b * SEQ + tid * 4]);
    float mx = fmaxf(fmaxf(v.x, v.y), fmaxf(v.z, v.w));
    #pragma unroll
    for (int o = 16; o; o >>= 1) mx = fmaxf(mx, __shfl_xor_sync(0xffffffffu, mx, o));
    if (lane == 0) red[warp] = mx;
    __syncthreads();
    mx = red[0];
    #pragma unroll
    for (int i = 1; i < 8; i++) mx = fmaxf(mx, red[i]);
    float e0 = expf(v.x - mx), e1 = expf(v.y - mx);
    float e2 = expf(v.z - mx), e3 = expf(v.w - mx);
    float s = e0 + e1 + e2 + e3;
    #pragma unroll
    for (int o = 16; o; o >>= 1) s += __shfl_xor_sync(0xffffffffu, s, o);
    __syncthreads();
    if (lane == 0) red[warp] = s;
    __syncthreads();
    s = 0.f;
    #pragma unroll
    for (int i = 0; i < 8; i++) s += red[i];
    float inv = 1.f / s;
    float4 o4 = make_float4(e0 * inv, e1 * inv, e2 * inv, e3 * inv);
    *reinterpret_cast<float4*>(&attn_out[b * SEQ + tid * 4]) = o4;
}

// ============================================================================
// Kernel D: context partials over s-eighths, then combine
// ============================================================================
__global__ void context_part_kernel(const float* __restrict__ ht,
                                    const float* __restrict__ attn) {
    __shared__ float w[128];
    int b = blockIdx.y;
    int h = blockIdx.x * 128 + threadIdx.x;
    int s0 = blockIdx.z * 128;
    if (threadIdx.x < 128) w[threadIdx.x] = attn[b * SEQ + s0 + threadIdx.x];
    __syncthreads();
    const float* p = ht + (size_t)s0 * (BATCH * H1D) + b * H1D + h;
    float a0 = 0.f, a1 = 0.f, a2 = 0.f, a3 = 0.f;
    #pragma unroll 4
    for (int s = 0; s < 128; s += 4) {
        a0 += w[s]     * p[(size_t)s * (BATCH * H1D)];
        a1 += w[s + 1] * p[(size_t)(s + 1) * (BATCH * H1D)];
        a2 += w[s + 2] * p[(size_t)(s + 2) * (BATCH * H1D)];
        a3 += w[s + 3] * p[(size_t)(s + 3) * (BATCH * H1D)];
    }
    g_part[blockIdx.z][b * H1D + h] = (a0 + a1) + (a2 + a3);
}

__global__ void context_combine_kernel(float* __restrict__ out_ctx) {
    int i = blockIdx.x * 256 + threadIdx.x;
    float s = 0.f;
    #pragma unroll
    for (int z = 0; z < 8; z++) s += g_part[z][i];
    out_ctx[i] = s;
}

// ============================================================================
extern "C" void kernel_launch(void* const* d_in, const int* in_sizes, int n_in,
                              void* d_out, int out_size) {
    const float* hs   = (const float*)d_in[0];
    const float* ht   = (const float*)d_in[1];
    const float* W1_w = (const float*)d_in[2];
    const float* W1_b = (const float*)d_in[3];
    const float* W2_w = (const float*)d_in[4];
    const float* W2_b = (const float*)d_in[5];
    const float* V_w  = (const float*)d_in[6];
    // d_in[7] = V_b: constant shift, cancels in softmax.

    float* out_ctx  = (float*)d_out;                 // (B, H1)
    float* out_attn = (float*)d_out + BATCH * H1D;   // (B, S, 1)

    __half* htH; cudaGetSymbolAddress((void**)&htH, g_htH);
    __half* W1H; cudaGetSymbolAddress((void**)&W1H, g_W1H);

    f2h_kernel<<<(size_t)MTOT * H1D / (256 * 8), 256>>>(ht, htH);
    f2h_kernel<<<(size_t)ATT * H1D / (256 * 8), 256>>>(W1_w, W1H);

    precompute_c_kernel<<<dim3(BATCH, ATT / 8), 256>>>(hs, W2_w, W1_b, W2_b);

    cudaFuncSetAttribute(energy_mma_kernel,
                         cudaFuncAttributeMaxDynamicSharedMemorySize, DYN_BYTES);
    energy_mma_kernel<<<MTOT / 128, 256, DYN_BYTES>>>(V_w);

    softmax_kernel<<<BATCH, 256>>>(out_attn);

    context_part_kernel<<<dim3(H1D / 128, BATCH, 8), 128>>>(ht, out_attn);
    context_combine_kernel<<<BATCH * H1D / 256, 256>>>(out_ctx);
}

// round 7
// speedup vs baseline: 3.7504x; 1.1361x over previous
#include <cuda_runtime.h>
#include <cuda_fp16.h>
#include <cstdint>
#include <cstddef>

#define BATCH 64
#define SEQ   1024
#define H1D   1024
#define ATT   1024
#define H2D   1024
#define MTOT  (SEQ * BATCH)

// ---------------- device scratch (no allocations allowed) ----------------
__device__ float  g_cT[ATT * BATCH];      // c transposed: g_cT[a*64 + b]
__device__ float  g_score[BATCH * SEQ];   // pre-softmax scores [b][s]
__device__ float  g_part[8][BATCH * H1D]; // context partials over s-eighths
__device__ __half g_htH[(size_t)MTOT * H1D]; // fp16 copy of ht (128 MB)
__device__ __half g_W1H[(size_t)ATT * H1D];  // fp16 copy of W1 (2 MB)

__device__ __forceinline__ float tanh_fast(float x) {
    float y;
    asm("tanh.approx.f32 %0, %1;" : "=f"(y) : "f"(x));
    return y;
}
__device__ __forceinline__ void cp16(uint32_t dst, const void* src) {
    asm volatile("cp.async.cg.shared.global [%0], [%1], 16;" :: "r"(dst), "l"(src));
}
__device__ __forceinline__ uint32_t smem_u32(const void* p) {
    uint32_t a;
    asm("{ .reg .u64 t; cvta.to.shared.u64 t, %1; cvt.u32.u64 %0, t; }"
        : "=r"(a) : "l"(p));
    return a;
}
__device__ __forceinline__ void ldsm_x4(uint32_t r[4], uint32_t addr) {
    asm volatile("ldmatrix.sync.aligned.m8n8.x4.shared.b16 {%0,%1,%2,%3}, [%4];"
                 : "=r"(r[0]), "=r"(r[1]), "=r"(r[2]), "=r"(r[3]) : "r"(addr));
}

// ============================================================================
// Kernel A0: fp32 -> fp16 bulk convert (8 elems/thread)
// ============================================================================
__global__ void f2h_kernel(const float* __restrict__ src, __half* __restrict__ dst) {
    size_t i = ((size_t)blockIdx.x * 256 + threadIdx.x) * 8;
    float4 a = *reinterpret_cast<const float4*>(src + i);
    float4 b = *reinterpret_cast<const float4*>(src + i + 4);
    __half2 h[4];
    h[0] = __floats2half2_rn(a.x, a.y);
    h[1] = __floats2half2_rn(a.z, a.w);
    h[2] = __floats2half2_rn(b.x, b.y);
    h[3] = __floats2half2_rn(b.z, b.w);
    *reinterpret_cast<uint4*>(dst + i) = *reinterpret_cast<uint4*>(h);
}

// ============================================================================
// Kernel A: c[b,a] -> transposed g_cT[a*64+b]
// ============================================================================
__global__ void precompute_c_kernel(const float* __restrict__ hs,
                                    const float* __restrict__ W2_w,
                                    const float* __restrict__ W1_b,
                                    const float* __restrict__ W2_b) {
    __shared__ float hsb[H2D];
    int b = blockIdx.x;
    for (int h = threadIdx.x; h < H2D; h += blockDim.x)
        hsb[h] = hs[(h >> 9) * (BATCH * 512) + b * 512 + (h & 511)];
    __syncthreads();
    int warp = threadIdx.x >> 5, lane = threadIdx.x & 31;
    int a = blockIdx.y * 8 + warp;
    const float* w2 = W2_w + (size_t)a * H2D;
    float acc = 0.f;
    for (int h = lane; h < H2D; h += 32) acc += w2[h] * hsb[h];
    #pragma unroll
    for (int o = 16; o; o >>= 1) acc += __shfl_xor_sync(0xffffffffu, acc, o);
    if (lane == 0) g_cT[a * BATCH + b] = acc + W1_b[a] + W2_b[a];
}

// ============================================================================
// Kernel B: fused energy/score GEMM, fp16 m16n8k16 HMMA, 2 CTAs/SM.
//   CTA tile: 64 rows x 256 cols per n-tile, NT=4, KC=32 halfs, 3-stage
//   cp.async pipeline. 8 warps, warp tile 32x64 (d[2][8][4] = 64 acc regs).
//   All 64 rows of a CTA share one s-index: s = blockIdx.x, b = local row.
// ============================================================================
#define KC       32                      // halfs per k-chunk
#define LDH_B    80                      // bytes per staged row (64 + 16 pad)
#define A_BYTES  (64 * LDH_B)            // 5120
#define B_BYTES  (256 * LDH_B)           // 20480
#define STAGE_BYTES (A_BYTES + B_BYTES)  // 25600
#define NSTAGE   3
#define DYN_BYTES (NSTAGE * STAGE_BYTES) // 76800

__device__ __forceinline__ void mma_f16(float d[4], uint32_t a0, uint32_t a1,
                                        uint32_t a2, uint32_t a3,
                                        uint32_t b0, uint32_t b1) {
    asm volatile(
        "mma.sync.aligned.m16n8k16.row.col.f32.f16.f16.f32 "
        "{%0,%1,%2,%3}, {%4,%5,%6,%7}, {%8,%9}, {%0,%1,%2,%3};"
        : "+f"(d[0]), "+f"(d[1]), "+f"(d[2]), "+f"(d[3])
        : "r"(a0), "r"(a1), "r"(a2), "r"(a3), "r"(b0), "r"(b1));
}

__global__ void __launch_bounds__(256, 2)
energy_mma_kernel(const float* __restrict__ V_w) {
    extern __shared__ char dynsm[];
    __shared__ float sV[ATT];
    __shared__ float part[4][64];

    const int tid  = threadIdx.x;
    const int warp = tid >> 5, lane = tid & 31;
    const int wm = warp >> 2;          // 0..1 : 32-row strip
    const int wn = warp & 3;           // 0..3 : 64-col strip
    const int q  = lane >> 2;          // 0..7
    const int c  = lane & 3;           // 0..3
    const int r0 = blockIdx.x * 64;    // s = blockIdx.x, b = local row

    for (int i = tid; i < ATT; i += 256) sV[i] = V_w[i];

    // staging map
    const uint32_t sb0 = smem_u32(dynsm);
    const int arow = tid >> 2, akq = tid & 3;   // A: 64 rows x 4 segs = 256
    const int brow = tid >> 2;                  // B rows 0..63 (+64j), 4 segs

    // ldmatrix per-lane byte offsets (within a stage)
    const int rr = lane & 7;
    const int gA_row = ((lane >> 3) & 1) * 8;
    const int gA_khi = ((lane >> 4) & 1) * 16;
    const int gB_row = ((lane >> 4) & 1) * 8;
    const int gB_khi = ((lane >> 3) & 1) * 16;
    uint32_t aoff[2], boff[4];
    #pragma unroll
    for (int mi = 0; mi < 2; mi++)
        aoff[mi] = (uint32_t)((wm * 32 + mi * 16 + rr + gA_row) * LDH_B + gA_khi);
    #pragma unroll
    for (int nj = 0; nj < 4; nj++)
        boff[nj] = (uint32_t)(A_BYTES +
                   (wn * 64 + nj * 16 + rr + gB_row) * LDH_B + gB_khi);

    float d[2][8][4];
    #pragma unroll
    for (int mi = 0; mi < 2; mi++)
        #pragma unroll
        for (int ni = 0; ni < 8; ni++)
            #pragma unroll
            for (int r = 0; r < 4; r++) d[mi][ni][r] = 0.f;
    float sc[4];
    #pragma unroll
    for (int i = 0; i < 4; i++) sc[i] = 0.f;

    auto issue = [&](int f) {
        const int st  = f % NSTAGE;
        const int k0h = (f & 31) * KC;
        const int n0  = (f >> 5) * 256;
        const uint32_t base = sb0 + (uint32_t)(st * STAGE_BYTES);
        cp16(base + (uint32_t)(arow * LDH_B + akq * 16),
             g_htH + (size_t)(r0 + arow) * H1D + k0h + akq * 8);
        #pragma unroll
        for (int j = 0; j < 4; j++) {
            int r = brow + j * 64;
            cp16(base + (uint32_t)(A_BYTES + r * LDH_B + akq * 16),
                 g_W1H + (size_t)(n0 + r) * H1D + k0h + akq * 8);
        }
    };

    issue(0); asm volatile("cp.async.commit_group;" ::: "memory");
    issue(1); asm volatile("cp.async.commit_group;" ::: "memory");

    const int F = 4 * 32;   // n-tiles * k-chunks
    for (int f = 0; f < F; f++) {
        asm volatile("cp.async.wait_group 1;" ::: "memory");
        __syncthreads();

        if (f + 2 < F) issue(f + 2);
        asm volatile("cp.async.commit_group;" ::: "memory");

        const uint32_t sbase = sb0 + (uint32_t)((f % NSTAGE) * STAGE_BYTES);

        #pragma unroll
        for (int kk = 0; kk < 2; kk++) {            // 2 k-steps of 16
            const uint32_t kadd = (uint32_t)(kk * 32);
            uint32_t af[2][4];
            #pragma unroll
            for (int mi = 0; mi < 2; mi++)
                ldsm_x4(af[mi], sbase + aoff[mi] + kadd);
            uint32_t bf[8][2];
            #pragma unroll
            for (int nj = 0; nj < 4; nj++) {
                uint32_t t[4];
                ldsm_x4(t, sbase + boff[nj] + kadd);
                bf[nj * 2][0] = t[0];     bf[nj * 2][1] = t[1];
                bf[nj * 2 + 1][0] = t[2]; bf[nj * 2 + 1][1] = t[3];
            }
            #pragma unroll
            for (int mi = 0; mi < 2; mi++)
                #pragma unroll
                for (int ni = 0; ni < 8; ni++)
                    mma_f16(d[mi][ni], af[mi][0], af[mi][1], af[mi][2],
                            af[mi][3], bf[ni][0], bf[ni][1]);
        }

        // ---- end of n-tile: fused tanh + V-dot, reset accumulators ----
        if ((f & 31) == 31) {
            const int n0 = (f >> 5) * 256;
            #pragma unroll
            for (int mi = 0; mi < 2; mi++) {
                const int rA = wm * 32 + mi * 16 + q;   // = batch index b
                float accA = 0.f, accB = 0.f;
                #pragma unroll
                for (int ni = 0; ni < 8; ni++) {
                    const int col = n0 + wn * 64 + ni * 8 + 2 * c;
                    const float v0 = sV[col], v1 = sV[col + 1];
                    const float* cb0 = &g_cT[col * BATCH];
                    const float* cb1 = &g_cT[(col + 1) * BATCH];
                    accA += v0 * tanh_fast(d[mi][ni][0] + __ldg(cb0 + rA))
                          + v1 * tanh_fast(d[mi][ni][1] + __ldg(cb1 + rA));
                    accB += v0 * tanh_fast(d[mi][ni][2] + __ldg(cb0 + rA + 8))
                          + v1 * tanh_fast(d[mi][ni][3] + __ldg(cb1 + rA + 8));
                    d[mi][ni][0] = 0.f; d[mi][ni][1] = 0.f;
                    d[mi][ni][2] = 0.f; d[mi][ni][3] = 0.f;
                }
                sc[mi * 2]     += accA;
                sc[mi * 2 + 1] += accB;
            }
        }
    }

    // ---- final reduction: quad shfl, then across wn warps via smem ----
    #pragma unroll
    for (int mi = 0; mi < 2; mi++)
        #pragma unroll
        for (int h = 0; h < 2; h++) {
            float v = sc[mi * 2 + h];
            v += __shfl_xor_sync(0xffffffffu, v, 1);
            v += __shfl_xor_sync(0xffffffffu, v, 2);
            if (c == 0)
                part[wn][wm * 32 + mi * 16 + q + 8 * h] = v;
        }
    __syncthreads();
    if (tid < 64) {
        float s = part[0][tid] + part[1][tid] + part[2][tid] + part[3][tid];
        g_score[tid * SEQ + blockIdx.x] = s;   // b = tid, s = blockIdx.x
    }
}

// ============================================================================
// Kernel C: softmax over S per batch
// ============================================================================
__global__ void softmax_kernel(float* __restrict__ attn_out) {
    __shared__ float red[8];
    int b = blockIdx.x, tid = threadIdx.x;
    int lane = tid & 31, warp = tid >> 5;
    float4 v = *reinterpret_cast<const float4*>(&g_score[b * SEQ + tid * 4]);
    float mx = fmaxf(fmaxf(v.x, v.y), fmaxf(v.z, v.w));
    #pragma unroll
    for (int o = 16; o; o >>= 1) mx = fmaxf(mx, __shfl_xor_sync(0xffffffffu, mx, o));
    if (lane == 0) red[warp] = mx;
    __syncthreads();
    mx = red[0];
    #pragma unroll
    for (int i = 1; i < 8; i++) mx = fmaxf(mx, red[i]);
    float e0 = expf(v.x - mx), e1 = expf(v.y - mx);
    float e2 = expf(v.z - mx), e3 = expf(v.w - mx);
    float s = e0 + e1 + e2 + e3;
    #pragma unroll
    for (int o = 16; o; o >>= 1) s += __shfl_xor_sync(0xffffffffu, s, o);
    __syncthreads();
    if (lane == 0) red[warp] = s;
    __syncthreads();
    s = 0.f;
    #pragma unroll
    for (int i = 0; i < 8; i++) s += red[i];
    float inv = 1.f / s;
    float4 o4 = make_float4(e0 * inv, e1 * inv, e2 * inv, e3 * inv);
    *reinterpret_cast<float4*>(&attn_out[b * SEQ + tid * 4]) = o4;
}

// ============================================================================
// Kernel D: context partials over s-eighths, then combine
// ============================================================================
__global__ void context_part_kernel(const float* __restrict__ ht,
                                    const float* __restrict__ attn) {
    __shared__ float w[128];
    int b = blockIdx.y;
    int h = blockIdx.x * 128 + threadIdx.x;
    int s0 = blockIdx.z * 128;
    if (threadIdx.x < 128) w[threadIdx.x] = attn[b * SEQ + s0 + threadIdx.x];
    __syncthreads();
    const float* p = ht + (size_t)s0 * (BATCH * H1D) + b * H1D + h;
    float a0 = 0.f, a1 = 0.f, a2 = 0.f, a3 = 0.f;
    #pragma unroll 4
    for (int s = 0; s < 128; s += 4) {
        a0 += w[s]     * p[(size_t)s * (BATCH * H1D)];
        a1 += w[s + 1] * p[(size_t)(s + 1) * (BATCH * H1D)];
        a2 += w[s + 2] * p[(size_t)(s + 2) * (BATCH * H1D)];
        a3 += w[s + 3] * p[(size_t)(s + 3) * (BATCH * H1D)];
    }
    g_part[blockIdx.z][b * H1D + h] = (a0 + a1) + (a2 + a3);
}

__global__ void context_combine_kernel(float* __restrict__ out_ctx) {
    int i = blockIdx.x * 256 + threadIdx.x;
    float s = 0.f;
    #pragma unroll
    for (int z = 0; z < 8; z++) s += g_part[z][i];
    out_ctx[i] = s;
}

// ============================================================================
extern "C" void kernel_launch(void* const* d_in, const int* in_sizes, int n_in,
                              void* d_out, int out_size) {
    const float* hs   = (const float*)d_in[0];
    const float* ht   = (const float*)d_in[1];
    const float* W1_w = (const float*)d_in[2];
    const float* W1_b = (const float*)d_in[3];
    const float* W2_w = (const float*)d_in[4];
    const float* W2_b = (const float*)d_in[5];
    const float* V_w  = (const float*)d_in[6];
    // d_in[7] = V_b: constant shift, cancels in softmax.

    float* out_ctx  = (float*)d_out;                 // (B, H1)
    float* out_attn = (float*)d_out + BATCH * H1D;   // (B, S, 1)

    __half* htH; cudaGetSymbolAddress((void**)&htH, g_htH);
    __half* W1H; cudaGetSymbolAddress((void**)&W1H, g_W1H);

    f2h_kernel<<<(size_t)MTOT * H1D / (256 * 8), 256>>>(ht, htH);
    f2h_kernel<<<(size_t)ATT * H1D / (256 * 8), 256>>>(W1_w, W1H);

    precompute_c_kernel<<<dim3(BATCH, ATT / 8), 256>>>(hs, W2_w, W1_b, W2_b);

    cudaFuncSetAttribute(energy_mma_kernel,
                         cudaFuncAttributeMaxDynamicSharedMemorySize, DYN_BYTES);
    energy_mma_kernel<<<MTOT / 64, 256, DYN_BYTES>>>(V_w);

    softmax_kernel<<<BATCH, 256>>>(out_attn);

    context_part_kernel<<<dim3(H1D / 128, BATCH, 8), 128>>>(ht, out_attn);
    context_combine_kernel<<<BATCH * H1D / 256, 256>>>(out_ctx);
}

// round 8
// speedup vs baseline: 3.8104x; 1.0160x over previous
#include <cuda_runtime.h>
#include <cuda_fp16.h>
#include <cstdint>
#include <cstddef>

#define BATCH 64
#define SEQ   1024
#define H1D   1024
#define ATT   1024
#define H2D   1024
#define MTOT  (SEQ * BATCH)

// ---------------- device scratch (no allocations allowed) ----------------
__device__ float  g_cT[ATT * BATCH];      // c transposed: g_cT[a*64 + b]
__device__ float  g_score[BATCH * SEQ];   // pre-softmax scores [b][s]
__device__ float  g_part[8][BATCH * H1D]; // context partials over s-eighths
__device__ __half g_htH[(size_t)MTOT * H1D]; // fp16 copy of ht (128 MB)
__device__ __half g_W1H[(size_t)ATT * H1D];  // fp16 copy of W1 (2 MB)

__device__ __forceinline__ float tanh_fast(float x) {
    float y;
    asm("tanh.approx.f32 %0, %1;" : "=f"(y) : "f"(x));
    return y;
}
__device__ __forceinline__ void cp16(uint32_t dst, const void* src) {
    asm volatile("cp.async.cg.shared.global [%0], [%1], 16;" :: "r"(dst), "l"(src));
}
__device__ __forceinline__ uint32_t smem_u32(const void* p) {
    uint32_t a;
    asm("{ .reg .u64 t; cvta.to.shared.u64 t, %1; cvt.u32.u64 %0, t; }"
        : "=r"(a) : "l"(p));
    return a;
}
__device__ __forceinline__ void ldsm_x4(uint32_t r[4], uint32_t addr) {
    asm volatile("ldmatrix.sync.aligned.m8n8.x4.shared.b16 {%0,%1,%2,%3}, [%4];"
                 : "=r"(r[0]), "=r"(r[1]), "=r"(r[2]), "=r"(r[3]) : "r"(addr));
}

// ============================================================================
// Kernel A0: fp32 -> fp16 bulk convert (8 elems/thread)
// ============================================================================
__global__ void f2h_kernel(const float* __restrict__ src, __half* __restrict__ dst) {
    size_t i = ((size_t)blockIdx.x * 256 + threadIdx.x) * 8;
    float4 a = *reinterpret_cast<const float4*>(src + i);
    float4 b = *reinterpret_cast<const float4*>(src + i + 4);
    __half2 h[4];
    h[0] = __floats2half2_rn(a.x, a.y);
    h[1] = __floats2half2_rn(a.z, a.w);
    h[2] = __floats2half2_rn(b.x, b.y);
    h[3] = __floats2half2_rn(b.z, b.w);
    *reinterpret_cast<uint4*>(dst + i) = *reinterpret_cast<uint4*>(h);
}

// ============================================================================
// Kernel A: c[b,a] -> transposed g_cT[a*64+b]
// ============================================================================
__global__ void precompute_c_kernel(const float* __restrict__ hs,
                                    const float* __restrict__ W2_w,
                                    const float* __restrict__ W1_b,
                                    const float* __restrict__ W2_b) {
    __shared__ float hsb[H2D];
    int b = blockIdx.x;
    for (int h = threadIdx.x; h < H2D; h += blockDim.x)
        hsb[h] = hs[(h >> 9) * (BATCH * 512) + b * 512 + (h & 511)];
    __syncthreads();
    int warp = threadIdx.x >> 5, lane = threadIdx.x & 31;
    int a = blockIdx.y * 8 + warp;
    const float* w2 = W2_w + (size_t)a * H2D;
    float acc = 0.f;
    for (int h = lane; h < H2D; h += 32) acc += w2[h] * hsb[h];
    #pragma unroll
    for (int o = 16; o; o >>= 1) acc += __shfl_xor_sync(0xffffffffu, acc, o);
    if (lane == 0) g_cT[a * BATCH + b] = acc + W1_b[a] + W2_b[a];
}

// ============================================================================
// Kernel B: fused energy/score GEMM, fp16 m16n8k16 HMMA, 2 CTAs/SM.
//   CTA tile: 64 rows x 256 cols per n-tile, NT=4 (order staggered by CTA
//   parity), KC=32 halfs, 4-stage cp.async pipeline. 8 warps, 32x64 warp tile.
// ============================================================================
#define KC       32                      // halfs per k-chunk
#define LDH_B    80                      // bytes per staged row (64 + 16 pad)
#define A_BYTES  (64 * LDH_B)            // 5120
#define B_BYTES  (256 * LDH_B)           // 20480
#define STAGE_BYTES (A_BYTES + B_BYTES)  // 25600
#define NSTAGE   4
#define DYN_BYTES (NSTAGE * STAGE_BYTES) // 102400

__device__ __forceinline__ void mma_f16(float d[4], uint32_t a0, uint32_t a1,
                                        uint32_t a2, uint32_t a3,
                                        uint32_t b0, uint32_t b1) {
    asm volatile(
        "mma.sync.aligned.m16n8k16.row.col.f32.f16.f16.f32 "
        "{%0,%1,%2,%3}, {%4,%5,%6,%7}, {%8,%9}, {%0,%1,%2,%3};"
        : "+f"(d[0]), "+f"(d[1]), "+f"(d[2]), "+f"(d[3])
        : "r"(a0), "r"(a1), "r"(a2), "r"(a3), "r"(b0), "r"(b1));
}

__global__ void __launch_bounds__(256, 2)
energy_mma_kernel(const float* __restrict__ V_w) {
    extern __shared__ char dynsm[];
    __shared__ float sV[ATT];
    __shared__ float part[4][64];

    const int tid  = threadIdx.x;
    const int warp = tid >> 5, lane = tid & 31;
    const int wm = warp >> 2;          // 0..1 : 32-row strip
    const int wn = warp & 3;           // 0..3 : 64-col strip
    const int q  = lane >> 2;          // 0..7
    const int c  = lane & 3;           // 0..3
    const int r0 = blockIdx.x * 64;    // s = blockIdx.x, b = local row
    const int phase = (blockIdx.x & 1) * 2;  // anti-phase n-tile order

    for (int i = tid; i < ATT; i += 256) sV[i] = V_w[i];

    // staging map
    const uint32_t sb0 = smem_u32(dynsm);
    const int arow = tid >> 2, akq = tid & 3;   // A: 64 rows x 4 segs = 256
    const int brow = tid >> 2;                  // B rows 0..63 (+64j), 4 segs

    // ldmatrix per-lane byte offsets (within a stage)
    const int rr = lane & 7;
    const int gA_row = ((lane >> 3) & 1) * 8;
    const int gA_khi = ((lane >> 4) & 1) * 16;
    const int gB_row = ((lane >> 4) & 1) * 8;
    const int gB_khi = ((lane >> 3) & 1) * 16;
    uint32_t aoff[2], boff[4];
    #pragma unroll
    for (int mi = 0; mi < 2; mi++)
        aoff[mi] = (uint32_t)((wm * 32 + mi * 16 + rr + gA_row) * LDH_B + gA_khi);
    #pragma unroll
    for (int nj = 0; nj < 4; nj++)
        boff[nj] = (uint32_t)(A_BYTES +
                   (wn * 64 + nj * 16 + rr + gB_row) * LDH_B + gB_khi);

    float d[2][8][4];
    #pragma unroll
    for (int mi = 0; mi < 2; mi++)
        #pragma unroll
        for (int ni = 0; ni < 8; ni++)
            #pragma unroll
            for (int r = 0; r < 4; r++) d[mi][ni][r] = 0.f;
    float sc[4];
    #pragma unroll
    for (int i = 0; i < 4; i++) sc[i] = 0.f;

    auto issue = [&](int f) {
        const int st  = f & (NSTAGE - 1);
        const int k0h = (f & 31) * KC;
        const int n0  = (((f >> 5) + phase) & 3) * 256;
        const uint32_t base = sb0 + (uint32_t)(st * STAGE_BYTES);
        cp16(base + (uint32_t)(arow * LDH_B + akq * 16),
             g_htH + (size_t)(r0 + arow) * H1D + k0h + akq * 8);
        #pragma unroll
        for (int j = 0; j < 4; j++) {
            int r = brow + j * 64;
            cp16(base + (uint32_t)(A_BYTES + r * LDH_B + akq * 16),
                 g_W1H + (size_t)(n0 + r) * H1D + k0h + akq * 8);
        }
    };

    issue(0); asm volatile("cp.async.commit_group;" ::: "memory");
    issue(1); asm volatile("cp.async.commit_group;" ::: "memory");
    issue(2); asm volatile("cp.async.commit_group;" ::: "memory");

    const int F = 4 * 32;   // n-tiles * k-chunks
    for (int f = 0; f < F; f++) {
        asm volatile("cp.async.wait_group 2;" ::: "memory");
        __syncthreads();

        if (f + 3 < F) issue(f + 3);
        asm volatile("cp.async.commit_group;" ::: "memory");

        const uint32_t sbase = sb0 + (uint32_t)((f & (NSTAGE - 1)) * STAGE_BYTES);

        #pragma unroll
        for (int kk = 0; kk < 2; kk++) {            // 2 k-steps of 16
            const uint32_t kadd = (uint32_t)(kk * 32);
            uint32_t af[2][4];
            #pragma unroll
            for (int mi = 0; mi < 2; mi++)
                ldsm_x4(af[mi], sbase + aoff[mi] + kadd);
            uint32_t bf[8][2];
            #pragma unroll
            for (int nj = 0; nj < 4; nj++) {
                uint32_t t[4];
                ldsm_x4(t, sbase + boff[nj] + kadd);
                bf[nj * 2][0] = t[0];     bf[nj * 2][1] = t[1];
                bf[nj * 2 + 1][0] = t[2]; bf[nj * 2 + 1][1] = t[3];
            }
            #pragma unroll
            for (int mi = 0; mi < 2; mi++)
                #pragma unroll
                for (int ni = 0; ni < 8; ni++)
                    mma_f16(d[mi][ni], af[mi][0], af[mi][1], af[mi][2],
                            af[mi][3], bf[ni][0], bf[ni][1]);
        }

        // ---- end of n-tile: fused tanh + V-dot, reset accumulators ----
        if ((f & 31) == 31) {
            const int n0 = (((f >> 5) + phase) & 3) * 256;
            #pragma unroll
            for (int mi = 0; mi < 2; mi++) {
                const int rA = wm * 32 + mi * 16 + q;   // = batch index b
                float accA = 0.f, accB = 0.f;
                #pragma unroll
                for (int ni = 0; ni < 8; ni++) {
                    const int col = n0 + wn * 64 + ni * 8 + 2 * c;
                    const float v0 = sV[col], v1 = sV[col + 1];
                    const float* cb0 = &g_cT[col * BATCH];
                    const float* cb1 = &g_cT[(col + 1) * BATCH];
                    accA += v0 * tanh_fast(d[mi][ni][0] + __ldg(cb0 + rA))
                          + v1 * tanh_fast(d[mi][ni][1] + __ldg(cb1 + rA));
                    accB += v0 * tanh_fast(d[mi][ni][2] + __ldg(cb0 + rA + 8))
                          + v1 * tanh_fast(d[mi][ni][3] + __ldg(cb1 + rA + 8));
                    d[mi][ni][0] = 0.f; d[mi][ni][1] = 0.f;
                    d[mi][ni][2] = 0.f; d[mi][ni][3] = 0.f;
                }
                sc[mi * 2]     += accA;
                sc[mi * 2 + 1] += accB;
            }
        }
    }

    // ---- final reduction: quad shfl, then across wn warps via smem ----
    #pragma unroll
    for (int mi = 0; mi < 2; mi++)
        #pragma unroll
        for (int h = 0; h < 2; h++) {
            float v = sc[mi * 2 + h];
            v += __shfl_xor_sync(0xffffffffu, v, 1);
            v += __shfl_xor_sync(0xffffffffu, v, 2);
            if (c == 0)
                part[wn][wm * 32 + mi * 16 + q + 8 * h] = v;
        }
    __syncthreads();
    if (tid < 64) {
        float s = part[0][tid] + part[1][tid] + part[2][tid] + part[3][tid];
        g_score[tid * SEQ + blockIdx.x] = s;   // b = tid, s = blockIdx.x
    }
}

// ============================================================================
// Kernel C: softmax over S per batch
// ============================================================================
__global__ void softmax_kernel(float* __restrict__ attn_out) {
    __shared__ float red[8];
    int b = blockIdx.x, tid = threadIdx.x;
    int lane = tid & 31, warp = tid >> 5;
    float4 v = *reinterpret_cast<const float4*>(&g_score[b * SEQ + tid * 4]);
    float mx = fmaxf(fmaxf(v.x, v.y), fmaxf(v.z, v.w));
    #pragma unroll
    for (int o = 16; o; o >>= 1) mx = fmaxf(mx, __shfl_xor_sync(0xffffffffu, mx, o));
    if (lane == 0) red[warp] = mx;
    __syncthreads();
    mx = red[0];
    #pragma unroll
    for (int i = 1; i < 8; i++) mx = fmaxf(mx, red[i]);
    float e0 = expf(v.x - mx), e1 = expf(v.y - mx);
    float e2 = expf(v.z - mx), e3 = expf(v.w - mx);
    float s = e0 + e1 + e2 + e3;
    #pragma unroll
    for (int o = 16; o; o >>= 1) s += __shfl_xor_sync(0xffffffffu, s, o);
    __syncthreads();
    if (lane == 0) red[warp] = s;
    __syncthreads();
    s = 0.f;
    #pragma unroll
    for (int i = 0; i < 8; i++) s += red[i];
    float inv = 1.f / s;
    float4 o4 = make_float4(e0 * inv, e1 * inv, e2 * inv, e3 * inv);
    *reinterpret_cast<float4*>(&attn_out[b * SEQ + tid * 4]) = o4;
}

// ============================================================================
// Kernel D: context partials from fp16 ht (half2), then combine
//   grid (H1D/256, BATCH, 8), block 128; each thread covers 2 h-values.
// ============================================================================
__global__ void context_part_kernel(const float* __restrict__ attn) {
    __shared__ float w[128];
    int b = blockIdx.y;
    int h2 = blockIdx.x * 128 + threadIdx.x;     // half2 index within row
    int s0 = blockIdx.z * 128;
    if (threadIdx.x < 128) w[threadIdx.x] = attn[b * SEQ + s0 + threadIdx.x];
    __syncthreads();
    const __half2* p = reinterpret_cast<const __half2*>(
        g_htH + (size_t)s0 * (BATCH * H1D) + b * H1D) + h2;
    const size_t stride2 = (size_t)BATCH * H1D / 2;
    float ax0 = 0.f, ay0 = 0.f, ax1 = 0.f, ay1 = 0.f;
    #pragma unroll 4
    for (int s = 0; s < 128; s += 2) {
        float2 f0 = __half22float2(p[(size_t)s * stride2]);
        float2 f1 = __half22float2(p[(size_t)(s + 1) * stride2]);
        ax0 += w[s] * f0.x;     ay0 += w[s] * f0.y;
        ax1 += w[s + 1] * f1.x; ay1 += w[s + 1] * f1.y;
    }
    float2 out = make_float2(ax0 + ax1, ay0 + ay1);
    *reinterpret_cast<float2*>(&g_part[blockIdx.z][b * H1D + h2 * 2]) = out;
}

__global__ void context_combine_kernel(float* __restrict__ out_ctx) {
    int i = blockIdx.x * 256 + threadIdx.x;
    float s = 0.f;
    #pragma unroll
    for (int z = 0; z < 8; z++) s += g_part[z][i];
    out_ctx[i] = s;
}

// ============================================================================
extern "C" void kernel_launch(void* const* d_in, const int* in_sizes, int n_in,
                              void* d_out, int out_size) {
    const float* hs   = (const float*)d_in[0];
    const float* ht   = (const float*)d_in[1];
    const float* W1_w = (const float*)d_in[2];
    const float* W1_b = (const float*)d_in[3];
    const float* W2_w = (const float*)d_in[4];
    const float* W2_b = (const float*)d_in[5];
    const float* V_w  = (const float*)d_in[6];
    // d_in[7] = V_b: constant shift, cancels in softmax.

    float* out_ctx  = (float*)d_out;                 // (B, H1)
    float* out_attn = (float*)d_out + BATCH * H1D;   // (B, S, 1)

    __half* htH; cudaGetSymbolAddress((void**)&htH, g_htH);
    __half* W1H; cudaGetSymbolAddress((void**)&W1H, g_W1H);

    f2h_kernel<<<(size_t)MTOT * H1D / (256 * 8), 256>>>(ht, htH);
    f2h_kernel<<<(size_t)ATT * H1D / (256 * 8), 256>>>(W1_w, W1H);

    precompute_c_kernel<<<dim3(BATCH, ATT / 8), 256>>>(hs, W2_w, W1_b, W2_b);

    cudaFuncSetAttribute(energy_mma_kernel,
                         cudaFuncAttributeMaxDynamicSharedMemorySize, DYN_BYTES);
    energy_mma_kernel<<<MTOT / 64, 256, DYN_BYTES>>>(V_w);

    softmax_kernel<<<BATCH, 256>>>(out_attn);

    context_part_kernel<<<dim3(H1D / 256, BATCH, 8), 128>>>(out_attn);
    context_combine_kernel<<<BATCH * H1D / 256, 256>>>(out_ctx);
}